// round 17
// baseline (speedup 1.0000x reference)
#include <cuda_runtime.h>
#include <cuda_bf16.h>

__device__ __forceinline__ float tanh_(float x){ float y; asm("tanh.approx.f32 %0, %1;" : "=f"(y) : "f"(x)); return y; }
__device__ __forceinline__ float ex2_(float x) { float y; asm("ex2.approx.f32 %0, %1;" : "=f"(y) : "f"(x)); return y; }
__device__ __forceinline__ float lg2_(float x) { float y; asm("lg2.approx.f32 %0, %1;" : "=f"(y) : "f"(x)); return y; }
__device__ __forceinline__ float sig_(float x) { return __frcp_rn(1.0f + ex2_(-1.44269504f * x)); }

// 32 blocks x 1024 threads, zero inter-block communication — the converged
// optimum (R12/R15: ~7.5-7.8us ncu / 8.67us wall, rel_err 5e-6). Only change:
// warps 8..31 (idle during the param phase) precompute their mask count
// pre-barrier; warps 0..7 keep it in the tail so their barrier-release chain
// is untouched.
__global__ void __launch_bounds__(1024, 1)
qlstm_all(const int*   __restrict__ x,    // (1024,128)
          const float* __restrict__ qw,   // (4,2,8)
          const float* __restrict__ Wo,   // (4,256,8)
          const float* __restrict__ bo,   // (4,256)
          const float* __restrict__ fcW,  // (2,256)
          const float* __restrict__ fcb,  // (2,)
          float*       __restrict__ out)  // (1024,2)
{
    const int tid  = threadIdx.x;
    const int lane = tid & 31;
    const int wrp  = tid >> 5;
    const int row  = blockIdx.x * 32 + wrp;      // this warp's batch row
    const unsigned FULL = 0xffffffffu;

    __shared__ float4 pA[256];                   // (f, ig, A=ig/(1-f), log2 f)
    __shared__ float2 pB[256];                   // (oo*fcW0, oo*fcW1)
    __shared__ float2 s_s[128];                  // s_t table

    // Mask slice: issue immediately.
    const int4 px = *(const int4*)(x + row * 128 + lane * 4);

    float inv_pre = 0.0f;                        // warps 8..31 fill this early

    // ---- Param phase: warps 0..7 only. All global loads issued FIRST so
    //      their latency overlaps the zeta/zz shuffle computation.
    if (tid < 256) {
        const int h = tid;
        float4 w0a = ((const float4*)(Wo + (0 * 256 + h) * 8))[0];
        float4 w0b = ((const float4*)(Wo + (0 * 256 + h) * 8))[1];
        float4 w1a = ((const float4*)(Wo + (1 * 256 + h) * 8))[0];
        float4 w1b = ((const float4*)(Wo + (1 * 256 + h) * 8))[1];
        float4 w2a = ((const float4*)(Wo + (2 * 256 + h) * 8))[0];
        float4 w2b = ((const float4*)(Wo + (2 * 256 + h) * 8))[1];
        float4 w3a = ((const float4*)(Wo + (3 * 256 + h) * 8))[0];
        float4 w3b = ((const float4*)(Wo + (3 * 256 + h) * 8))[1];
        float b0 = bo[0 * 256 + h], b1 = bo[1 * 256 + h];
        float b2 = bo[2 * 256 + h], b3 = bo[3 * 256 + h];
        float fc0 = fcW[h], fc1 = fcW[256 + h];

        // zeta[g][j] = -sin(qw[g,0,j])  (H->RX is a global phase; RZ drops).
        // Lane (g=lane>>3, j=lane&7); CNOT-ring products zz via shuffles,
        // fully overlapped with the outstanding loads above.
        const int g_ = lane >> 3, j_ = lane & 7;
        const float zeta = -__sinf(qw[g_ * 16 + j_]);
        const int base = lane & 24;              // g*8
        float zzv = 1.0f;
#pragma unroll
        for (int j2 = 0; j2 < 8; j2++) {
            float zj = __shfl_sync(FULL, zeta, base + j2);
            bool incl = (j_ == 0) ? (j2 >= 1) : (j2 <= j_);
            zzv = incl ? zzv * zj : zzv;
        }
        // pre[g] = bo + Wo[g,h,:] . zz[g,:]  (zz gathered by shuffle)
        float pre0 = b0, pre1 = b1, pre2 = b2, pre3 = b3;
#pragma unroll
        for (int q = 0; q < 4; q++) {
            float z0 = __shfl_sync(FULL, zzv,  0 + q);
            float z4 = __shfl_sync(FULL, zzv,  4 + q);
            float z8 = __shfl_sync(FULL, zzv,  8 + q);
            float z12= __shfl_sync(FULL, zzv, 12 + q);
            float z16= __shfl_sync(FULL, zzv, 16 + q);
            float z20= __shfl_sync(FULL, zzv, 20 + q);
            float z24= __shfl_sync(FULL, zzv, 24 + q);
            float z28= __shfl_sync(FULL, zzv, 28 + q);
            const float* a;
            a = (const float*)&w0a; pre0 += a[q] * z0;
            a = (const float*)&w0b; pre0 += a[q] * z4;
            a = (const float*)&w1a; pre1 += a[q] * z8;
            a = (const float*)&w1b; pre1 += a[q] * z12;
            a = (const float*)&w2a; pre2 += a[q] * z16;
            a = (const float*)&w2b; pre2 += a[q] * z20;
            a = (const float*)&w3a; pre3 += a[q] * z24;
            a = (const float*)&w3b; pre3 += a[q] * z28;
        }

        const float e   = ex2_(-1.44269504f * pre0);
        const float ope = 1.0f + e;
        const float f_  = __frcp_rn(ope);            // sigmoid(pre0)
        const float lf2 = -lg2_(ope);                // log2(f)
        const float ig_ = sig_(pre1) * tanh_(pre2);
        const float oo_ = sig_(pre3);
        const float omf = __fdividef(e, ope);        // 1 - f
        const float A_  = ig_ * __frcp_rn(omf);      // c_inf
        pA[h] = make_float4(f_, ig_, A_, lf2);
        pB[h] = make_float2(oo_ * fc0, oo_ * fc1);
    } else {
        // Warps 8..31: idle during param phase -> precompute mask count now.
        unsigned bx = __ballot_sync(FULL, px.x != 0);
        unsigned by = __ballot_sync(FULL, px.y != 0);
        unsigned bz = __ballot_sync(FULL, px.z != 0);
        unsigned bw = __ballot_sync(FULL, px.w != 0);
        float cnt = (float)(__popc(bx) + __popc(by) + __popc(bz) + __popc(bw));
        inv_pre = __frcp_rn(cnt + 1e-9f);
    }
    __syncthreads();

    // ---- Sweep: warp w owns t in [4w,4w+4); lane owns h in {lane+32k}.
    //      fp32 closed-form jump c_{4w} = A(1-f^{4w}), then 4 exact steps.
    {
        const float n0 = (float)(4 * wrp);
        float a00 = 0.f, a01 = 0.f, a02 = 0.f, a03 = 0.f;   // class 0
        float a10 = 0.f, a11 = 0.f, a12 = 0.f, a13 = 0.f;   // class 1
#pragma unroll
        for (int k = 0; k < 8; k++) {
            const int h = lane + 32 * k;
            const float4 P = pA[h];
            const float2 Q = pB[h];
            float c = P.z - P.z * ex2_(n0 * P.w);
            float th;
            c = fmaf(P.x, c, P.y); th = tanh_(c); a00 += Q.x * th; a10 += Q.y * th;
            c = fmaf(P.x, c, P.y); th = tanh_(c); a01 += Q.x * th; a11 += Q.y * th;
            c = fmaf(P.x, c, P.y); th = tanh_(c); a02 += Q.x * th; a12 += Q.y * th;
            c = fmaf(P.x, c, P.y); th = tanh_(c); a03 += Q.x * th; a13 += Q.y * th;
        }
        // In-warp butterfly: h-reduction across the 32 lanes
#pragma unroll
        for (int off = 16; off; off >>= 1) {
            a00 += __shfl_xor_sync(FULL, a00, off);
            a01 += __shfl_xor_sync(FULL, a01, off);
            a02 += __shfl_xor_sync(FULL, a02, off);
            a03 += __shfl_xor_sync(FULL, a03, off);
            a10 += __shfl_xor_sync(FULL, a10, off);
            a11 += __shfl_xor_sync(FULL, a11, off);
            a12 += __shfl_xor_sync(FULL, a12, off);
            a13 += __shfl_xor_sync(FULL, a13, off);
        }
        if (lane == 0) {
            s_s[4 * wrp + 0] = make_float2(a00, a10);
            s_s[4 * wrp + 1] = make_float2(a01, a11);
            s_s[4 * wrp + 2] = make_float2(a02, a12);
            s_s[4 * wrp + 3] = make_float2(a03, a13);
        }
    }
    __syncthreads();

    // ---- Stage 2: masks (in regs since start) x s table (vectorized LDS).
    //      Warps 0..7 compute cnt here; warps 8..31 already have inv_pre.
    const float4* st = (const float4*)s_s;
    float4 sa = st[lane * 2 + 0];
    float4 sb = st[lane * 2 + 1];
    float inv;
    if (wrp < 8) {
        unsigned bx = __ballot_sync(FULL, px.x != 0);
        unsigned by = __ballot_sync(FULL, px.y != 0);
        unsigned bz = __ballot_sync(FULL, px.z != 0);
        unsigned bw = __ballot_sync(FULL, px.w != 0);
        float cnt = (float)(__popc(bx) + __popc(by) + __popc(bz) + __popc(bw));
        inv = __frcp_rn(cnt + 1e-9f);
    } else {
        inv = inv_pre;
    }
    float a0 = 0.0f, a1 = 0.0f, m;
    m = (px.x != 0) ? 1.0f : 0.0f; a0 += m * sa.x; a1 += m * sa.y;
    m = (px.y != 0) ? 1.0f : 0.0f; a0 += m * sa.z; a1 += m * sa.w;
    m = (px.z != 0) ? 1.0f : 0.0f; a0 += m * sb.x; a1 += m * sb.y;
    m = (px.w != 0) ? 1.0f : 0.0f; a0 += m * sb.z; a1 += m * sb.w;
#pragma unroll
    for (int off = 16; off; off >>= 1) {
        a0 += __shfl_xor_sync(FULL, a0, off);
        a1 += __shfl_xor_sync(FULL, a1, off);
    }
    if (lane == 0) {
        float2 o = make_float2(fmaf(a0, inv, fcb[0]), fmaf(a1, inv, fcb[1]));
        *(float2*)(out + row * 2) = o;
    }
}

extern "C" void kernel_launch(void* const* d_in, const int* in_sizes, int n_in,
                              void* d_out, int out_size)
{
    // metadata order: x, embed, Wi, bi, qw, Wo, bo, fcW, fcb
    const int*   x   = (const int*)  d_in[0];
    const float* qw  = (const float*)d_in[4];
    const float* Wo  = (const float*)d_in[5];
    const float* bo  = (const float*)d_in[6];
    const float* fcW = (const float*)d_in[7];
    const float* fcb = (const float*)d_in[8];
    float* out = (float*)d_out;

    qlstm_all<<<32, 1024>>>(x, qw, Wo, bo, fcW, fcb, out);

    (void)in_sizes; (void)n_in; (void)out_size;
}